// round 7
// baseline (speedup 1.0000x reference)
#include <cuda_runtime.h>
#include <cuda_bf16.h>

#define B_SIZE 16384
#define K_NEG  20
#define DIM    128
#define NBLOCKS (B_SIZE / 4)   // 4 warps/block, 1 row/warp

// Cross-block accumulator state. Statically zero-initialized; the last block
// of every launch resets it to zero, so every graph replay sees a clean state.
__device__ float        g_acc  = 0.0f;
__device__ unsigned int g_done = 0u;

__device__ __forceinline__ float warp_sum(float v) {
    v += __shfl_xor_sync(0xffffffffu, v, 16);
    v += __shfl_xor_sync(0xffffffffu, v, 8);
    v += __shfl_xor_sync(0xffffffffu, v, 4);
    v += __shfl_xor_sync(0xffffffffu, v, 2);
    v += __shfl_xor_sync(0xffffffffu, v, 1);
    return v;
}

// Fast, stable log(sigmoid(x)) = min(x,0) - log(1 + exp(-|x|))
__device__ __forceinline__ float log_sigmoid_fast(float x) {
    return fminf(x, 0.0f) - __logf(1.0f + __expf(-fabsf(x)));
}

__global__ __launch_bounds__(128) void skipgram_kernel(
    const int* __restrict__ target,
    const int* __restrict__ context,
    const int* __restrict__ negs,
    const float* __restrict__ in_embed,
    const float* __restrict__ out_embed,
    float* __restrict__ out)
{
    const int lane = threadIdx.x & 31;
    const int warp_in_block = threadIdx.x >> 5;
    // grid is exact: 16384 rows / (4 warps/block) = 4096 blocks, no bounds check.
    const int b = blockIdx.x * 4 + warp_in_block;

    // One coalesced index load for the whole warp:
    // lane 0..19 -> neg index k=lane ; lane 20..31 -> context index (uniform).
    const int* nb = negs + (size_t)b * K_NEG;
    const int idx = (lane < K_NEG) ? __ldg(nb + lane) : __ldg(context + b);

    // Each lane owns 4 consecutive floats of the 128-float row.
    const float4 tv = reinterpret_cast<const float4*>(
        in_embed + (size_t)__ldg(target + b) * DIM)[lane];

    // v[k] = this lane's partial dot for value k.
    // k in [0,20): negative scores; k == 20: positive; k > 20: don't-care.
    float v[32];

    #pragma unroll
    for (int k = 0; k <= K_NEG; k++) {
        const int row = __shfl_sync(0xffffffffu, idx, k);
        const float4 nv = reinterpret_cast<const float4*>(
            out_embed + (size_t)row * DIM)[lane];
        v[k] = tv.x * nv.x + tv.y * nv.y + tv.z * nv.z + tv.w * nv.w;
    }
    #pragma unroll
    for (int j = K_NEG + 1; j < 32; j++) v[j] = v[K_NEG];  // cheap pad (reg copy)

    // Packed butterfly transpose-reduce: after 5 stages, v[0] on lane L holds
    // the fully lane-summed score for value L. 31 shuffles total.
    #pragma unroll
    for (int i = 0; i < 5; i++) {
        const int off = 1 << i;
        const bool par = (lane >> i) & 1;
        const int n = 32 >> i;
        #pragma unroll
        for (int j = 0; j < n / 2; j++) {
            const float a = v[2 * j];
            const float c = v[2 * j + 1];
            const float send = par ? a : c;
            const float keep = par ? c : a;
            const float got = __shfl_xor_sync(0xffffffffu, send, off);
            v[j] = keep + got;
        }
    }

    const float s = v[0];                    // score for value index == lane
    const float x = (lane == K_NEG) ? s : -s;
    float contrib = (lane <= K_NEG) ? log_sigmoid_fast(x) : 0.0f;

    // Sum the 21 per-lane loss terms of this row, then block-reduce.
    contrib = warp_sum(contrib);

    __shared__ float smem[4];
    if (lane == 0) smem[warp_in_block] = contrib;
    __syncthreads();

    if (threadIdx.x == 0) {
        const float blk = smem[0] + smem[1] + smem[2] + smem[3];
        atomicAdd(&g_acc, blk);
        // Make this block's contribution visible before taking a ticket.
        __threadfence();
        const unsigned t = atomicAdd(&g_done, 1u);
        if (t == (unsigned)(NBLOCKS - 1)) {
            // Last block: every other block's g_acc add is visible now.
            out[0] = -g_acc * (1.0f / (float)B_SIZE);
            // Reset state for the next graph replay.
            g_acc  = 0.0f;
            g_done = 0u;
        }
    }
}

extern "C" void kernel_launch(void* const* d_in, const int* in_sizes, int n_in,
                              void* d_out, int out_size) {
    const int*   target    = (const int*)d_in[0];
    const int*   context   = (const int*)d_in[1];
    const int*   negs      = (const int*)d_in[2];
    const float* in_embed  = (const float*)d_in[3];
    const float* out_embed = (const float*)d_in[4];
    float*       out       = (float*)d_out;

    // Single kernel: 4 warps/block, one row/warp; 16384/4 = 4096 blocks exact.
    skipgram_kernel<<<NBLOCKS, 128>>>(
        target, context, negs, in_embed, out_embed, out);
}

// round 8
// speedup vs baseline: 1.0574x; 1.0574x over previous
#include <cuda_runtime.h>
#include <cuda_bf16.h>

#define B_SIZE 16384
#define K_NEG  20
#define DIM    128
#define NBLOCKS (B_SIZE / 4)   // 4 warps/block, 1 row/warp

// Cross-block accumulator state. Statically zero-initialized; the last block
// of every launch resets it, so every graph replay sees a clean state.
__device__ float        g_acc  = 0.0f;
__device__ unsigned int g_done = 0u;

__device__ __forceinline__ float warp_sum(float v) {
    v += __shfl_xor_sync(0xffffffffu, v, 16);
    v += __shfl_xor_sync(0xffffffffu, v, 8);
    v += __shfl_xor_sync(0xffffffffu, v, 4);
    v += __shfl_xor_sync(0xffffffffu, v, 2);
    v += __shfl_xor_sync(0xffffffffu, v, 1);
    return v;
}

// Fast, stable log(sigmoid(x)) = min(x,0) - log(1 + exp(-|x|))
__device__ __forceinline__ float log_sigmoid_fast(float x) {
    return fminf(x, 0.0f) - __logf(1.0f + __expf(-fabsf(x)));
}

__global__ __launch_bounds__(128) void skipgram_kernel(
    const int* __restrict__ target,
    const int* __restrict__ context,
    const int* __restrict__ negs,
    const float* __restrict__ in_embed,
    const float* __restrict__ out_embed,
    float* __restrict__ out)
{
    const int lane = threadIdx.x & 31;
    const int warp_in_block = threadIdx.x >> 5;
    // grid is exact: 16384 rows / (4 warps/block) = 4096 blocks, no bounds check.
    const int b = blockIdx.x * 4 + warp_in_block;

    // One coalesced index load for the whole warp:
    // lane 0..19 -> neg index k=lane ; lane 20..31 -> context index (uniform).
    const int* nb = negs + (size_t)b * K_NEG;
    const int idx = (lane < K_NEG) ? __ldg(nb + lane) : __ldg(context + b);

    // Each lane owns 4 consecutive floats of the 128-float row.
    const float4 tv = reinterpret_cast<const float4*>(
        in_embed + (size_t)__ldg(target + b) * DIM)[lane];

    // v[k] = this lane's partial dot for value k.
    // k in [0,20): negative scores; k == 20: positive; k > 20: don't-care.
    float v[32];

    #pragma unroll
    for (int k = 0; k <= K_NEG; k++) {
        const int row = __shfl_sync(0xffffffffu, idx, k);
        const float4 nv = reinterpret_cast<const float4*>(
            out_embed + (size_t)row * DIM)[lane];
        v[k] = tv.x * nv.x + tv.y * nv.y + tv.z * nv.z + tv.w * nv.w;
    }
    #pragma unroll
    for (int j = K_NEG + 1; j < 32; j++) v[j] = v[K_NEG];  // cheap pad (reg copy)

    // Packed butterfly transpose-reduce: after 5 stages, v[0] on lane L holds
    // the fully lane-summed score for value L. 31 shuffles total.
    #pragma unroll
    for (int i = 0; i < 5; i++) {
        const int off = 1 << i;
        const bool par = (lane >> i) & 1;
        const int n = 32 >> i;
        #pragma unroll
        for (int j = 0; j < n / 2; j++) {
            const float a = v[2 * j];
            const float c = v[2 * j + 1];
            const float send = par ? a : c;
            const float keep = par ? c : a;
            const float got = __shfl_xor_sync(0xffffffffu, send, off);
            v[j] = keep + got;
        }
    }

    const float s = v[0];                    // score for value index == lane
    const float x = (lane == K_NEG) ? s : -s;
    float contrib = (lane <= K_NEG) ? log_sigmoid_fast(x) : 0.0f;

    // Sum the 21 per-lane loss terms of this row, then block-reduce.
    contrib = warp_sum(contrib);

    __shared__ float smem[4];
    if (lane == 0) smem[warp_in_block] = contrib;
    __syncthreads();

    if (threadIdx.x == 0) {
        const float blk = smem[0] + smem[1] + smem[2] + smem[3];
        // Relaxed accumulate (performed at L2).
        atomicAdd(&g_acc, blk);
        // Ticket with acq_rel, gpu scope: the RELEASE half orders this block's
        // g_acc add before the ticket becomes visible (no L1D invalidate, unlike
        // __threadfence); the ACQUIRE half makes all released g_acc adds visible
        // to whichever block draws the last ticket.
        unsigned t;
        asm volatile("atom.acq_rel.gpu.add.u32 %0, [%1], %2;"
                     : "=r"(t) : "l"(&g_done), "r"(1u) : "memory");
        if (t == (unsigned)(NBLOCKS - 1)) {
            float total;
            asm volatile("ld.global.cg.f32 %0, [%1];"
                         : "=f"(total) : "l"(&g_acc) : "memory");
            out[0] = -total * (1.0f / (float)B_SIZE);
            // Reset state for the next graph replay (visible at kernel boundary).
            asm volatile("st.global.cg.f32 [%0], %1;"
                         :: "l"(&g_acc), "f"(0.0f) : "memory");
            asm volatile("st.global.cg.u32 [%0], %1;"
                         :: "l"(&g_done), "r"(0u) : "memory");
        }
    }
}

extern "C" void kernel_launch(void* const* d_in, const int* in_sizes, int n_in,
                              void* d_out, int out_size) {
    const int*   target    = (const int*)d_in[0];
    const int*   context   = (const int*)d_in[1];
    const int*   negs      = (const int*)d_in[2];
    const float* in_embed  = (const float*)d_in[3];
    const float* out_embed = (const float*)d_in[4];
    float*       out       = (float*)d_out;

    // Single kernel: 4 warps/block, one row/warp; 16384/4 = 4096 blocks exact.
    skipgram_kernel<<<NBLOCKS, 128>>>(
        target, context, negs, in_embed, out_embed, out);
}

// round 12
// speedup vs baseline: 1.1218x; 1.0609x over previous
#include <cuda_runtime.h>
#include <cuda_bf16.h>

#define B_SIZE 16384
#define K_NEG  20
#define DIM    128
#define NBLOCKS (B_SIZE / 4)   // 4 warps/block, 1 row/warp

// Cross-block accumulator state. Statically zero-initialized; the last block
// of every launch resets it, so every graph replay sees a clean state.
__device__ float        g_acc  = 0.0f;
__device__ unsigned int g_done = 0u;

__device__ __forceinline__ float warp_sum(float v) {
    v += __shfl_xor_sync(0xffffffffu, v, 16);
    v += __shfl_xor_sync(0xffffffffu, v, 8);
    v += __shfl_xor_sync(0xffffffffu, v, 4);
    v += __shfl_xor_sync(0xffffffffu, v, 2);
    v += __shfl_xor_sync(0xffffffffu, v, 1);
    return v;
}

// Fast, stable log(sigmoid(x)) = min(x,0) - log(1 + exp(-|x|))
__device__ __forceinline__ float log_sigmoid_fast(float x) {
    return fminf(x, 0.0f) - __logf(1.0f + __expf(-fabsf(x)));
}

__global__ __launch_bounds__(128) void skipgram_kernel(
    const int* __restrict__ target,
    const int* __restrict__ context,
    const int* __restrict__ negs,
    const float* __restrict__ in_embed,
    const float* __restrict__ out_embed,
    float* __restrict__ out)
{
    const int lane = threadIdx.x & 31;
    const int warp_in_block = threadIdx.x >> 5;
    // grid is exact: 16384 rows / (4 warps/block) = 4096 blocks, no bounds check.
    const int b = blockIdx.x * 4 + warp_in_block;

    // One coalesced index load for the whole warp:
    // lane 0..19 -> neg index k=lane ; lane 20..31 -> context index (uniform).
    const int* nb = negs + (size_t)b * K_NEG;
    const int idx = (lane < K_NEG) ? __ldg(nb + lane) : __ldg(context + b);

    // Each lane owns 4 consecutive floats of the 128-float row.
    const float4 tv = reinterpret_cast<const float4*>(
        in_embed + (size_t)__ldg(target + b) * DIM)[lane];

    // v[k] = this lane's partial dot for value k.
    // k in [0,20): negative scores; k == 20: positive; k > 20: don't-care.
    float v[32];

    #pragma unroll
    for (int k = 0; k <= K_NEG; k++) {
        const int row = __shfl_sync(0xffffffffu, idx, k);
        const float4 nv = reinterpret_cast<const float4*>(
            out_embed + (size_t)row * DIM)[lane];
        v[k] = tv.x * nv.x + tv.y * nv.y + tv.z * nv.z + tv.w * nv.w;
    }
    #pragma unroll
    for (int j = K_NEG + 1; j < 32; j++) v[j] = v[K_NEG];  // cheap pad (reg copy)

    // Packed butterfly transpose-reduce: after 5 stages, v[0] on lane L holds
    // the fully lane-summed score for value L. 31 shuffles total.
    #pragma unroll
    for (int i = 0; i < 5; i++) {
        const int off = 1 << i;
        const bool par = (lane >> i) & 1;
        const int n = 32 >> i;
        #pragma unroll
        for (int j = 0; j < n / 2; j++) {
            const float a = v[2 * j];
            const float c = v[2 * j + 1];
            const float send = par ? a : c;
            const float keep = par ? c : a;
            const float got = __shfl_xor_sync(0xffffffffu, send, off);
            v[j] = keep + got;
        }
    }

    const float s = v[0];                    // score for value index == lane
    const float x = (lane == K_NEG) ? s : -s;
    float contrib = (lane <= K_NEG) ? log_sigmoid_fast(x) : 0.0f;

    // Sum the 21 per-lane loss terms of this row, then block-reduce.
    contrib = warp_sum(contrib);

    __shared__ float smem[4];
    if (lane == 0) smem[warp_in_block] = contrib;
    __syncthreads();

    if (threadIdx.x == 0) {
        const float blk = smem[0] + smem[1] + smem[2] + smem[3];
        // Relaxed accumulate: REDG.F32 performed at L2. No fence, no acquire.
        atomicAdd(&g_acc, blk);
        // Ticket with RELEASE-ONLY semantics: orders this block's g_acc add
        // before the ticket becomes visible. Release flushes stores — it does
        // NOT invalidate L1 (that's acquire), so other blocks are unaffected.
        unsigned t;
        asm volatile("atom.release.gpu.global.add.u32 %0, [%1], %2;"
                     : "=r"(t) : "l"(&g_done), "r"(1u) : "memory");
        if (t == (unsigned)(NBLOCKS - 1)) {
            // All tickets drawn => every block's release happened => every
            // g_acc add is performed at L2. Read it via the L2 atomic path
            // (RMW sees L2 directly) — no acquire needed.
            const float total = atomicAdd(&g_acc, 0.0f);
            out[0] = -total * (1.0f / (float)B_SIZE);
            // Reset state for the next graph replay (L2 RMWs; the kernel
            // boundary orders them before the next launch's reads).
            atomicExch(&g_acc, 0.0f);
            atomicExch(&g_done, 0u);
        }
    }
}

extern "C" void kernel_launch(void* const* d_in, const int* in_sizes, int n_in,
                              void* d_out, int out_size) {
    const int*   target    = (const int*)d_in[0];
    const int*   context   = (const int*)d_in[1];
    const int*   negs      = (const int*)d_in[2];
    const float* in_embed  = (const float*)d_in[3];
    const float* out_embed = (const float*)d_in[4];
    float*       out       = (float*)d_out;

    // Single kernel: 4 warps/block, one row/warp; 16384/4 = 4096 blocks exact.
    skipgram_kernel<<<NBLOCKS, 128>>>(
        target, context, negs, in_embed, out_embed, out);
}

// round 17
// speedup vs baseline: 1.1471x; 1.0225x over previous
#include <cuda_runtime.h>
#include <cuda_bf16.h>

#define B_SIZE 16384
#define K_NEG  20
#define DIM    128

__device__ __forceinline__ float warp_sum(float v) {
    v += __shfl_xor_sync(0xffffffffu, v, 16);
    v += __shfl_xor_sync(0xffffffffu, v, 8);
    v += __shfl_xor_sync(0xffffffffu, v, 4);
    v += __shfl_xor_sync(0xffffffffu, v, 2);
    v += __shfl_xor_sync(0xffffffffu, v, 1);
    return v;
}

// Fast, stable log(sigmoid(x)) = min(x,0) - log(1 + exp(-|x|))
__device__ __forceinline__ float log_sigmoid_fast(float x) {
    return fminf(x, 0.0f) - __logf(1.0f + __expf(-fabsf(x)));
}

__global__ __launch_bounds__(128) void skipgram_kernel(
    const int* __restrict__ target,
    const int* __restrict__ context,
    const int* __restrict__ negs,
    const float* __restrict__ in_embed,
    const float* __restrict__ out_embed,
    float* __restrict__ out)
{
    const int lane = threadIdx.x & 31;
    const int warp_in_block = threadIdx.x >> 5;
    // grid is exact: 16384 rows / (4 warps/block) = 4096 blocks, no bounds check.
    const int b = blockIdx.x * 4 + warp_in_block;

    // One coalesced index load for the whole warp:
    // lane 0..19 -> neg index k=lane ; lane 20..31 -> context index (uniform).
    const int* nb = negs + (size_t)b * K_NEG;
    const int idx = (lane < K_NEG) ? __ldg(nb + lane) : __ldg(context + b);

    // Each lane owns 4 consecutive floats of the 128-float row.
    const float4 tv = reinterpret_cast<const float4*>(
        in_embed + (size_t)__ldg(target + b) * DIM)[lane];

    // v[k] = this lane's partial dot for value k.
    // k in [0,20): negative scores; k == 20: positive; k > 20: don't-care.
    float v[32];

    #pragma unroll
    for (int k = 0; k <= K_NEG; k++) {
        const int row = __shfl_sync(0xffffffffu, idx, k);
        const float4 nv = reinterpret_cast<const float4*>(
            out_embed + (size_t)row * DIM)[lane];
        v[k] = tv.x * nv.x + tv.y * nv.y + tv.z * nv.z + tv.w * nv.w;
    }
    #pragma unroll
    for (int j = K_NEG + 1; j < 32; j++) v[j] = v[K_NEG];  // cheap pad (reg copy)

    // Packed butterfly transpose-reduce: after 5 stages, v[0] on lane L holds
    // the fully lane-summed score for value L. 31 shuffles total.
    #pragma unroll
    for (int i = 0; i < 5; i++) {
        const int off = 1 << i;
        const bool par = (lane >> i) & 1;
        const int n = 32 >> i;
        #pragma unroll
        for (int j = 0; j < n / 2; j++) {
            const float a = v[2 * j];
            const float c = v[2 * j + 1];
            const float send = par ? a : c;
            const float keep = par ? c : a;
            const float got = __shfl_xor_sync(0xffffffffu, send, off);
            v[j] = keep + got;
        }
    }

    const float s = v[0];                    // score for value index == lane
    const float x = (lane == K_NEG) ? s : -s;
    float contrib = (lane <= K_NEG) ? log_sigmoid_fast(x) : 0.0f;

    // Sum the 21 per-lane loss terms of this row, then block-reduce.
    contrib = warp_sum(contrib);

    __shared__ float smem[4];
    if (lane == 0) smem[warp_in_block] = contrib;
    __syncthreads();

    if (threadIdx.x == 0) {
        const float acc = smem[0] + smem[1] + smem[2] + smem[3];
        atomicAdd(out, -acc * (1.0f / (float)B_SIZE));
    }
}

extern "C" void kernel_launch(void* const* d_in, const int* in_sizes, int n_in,
                              void* d_out, int out_size) {
    const int*   target    = (const int*)d_in[0];
    const int*   context   = (const int*)d_in[1];
    const int*   negs      = (const int*)d_in[2];
    const float* in_embed  = (const float*)d_in[3];
    const float* out_embed = (const float*)d_in[4];
    float*       out       = (float*)d_out;

    // Zero the scalar output with a memset node (graph-capturable, cheaper
    // than a kernel node; 0.0f is all-zero bytes).
    cudaMemsetAsync(out, 0, sizeof(float));

    // 4 warps per block, one batch row per warp; 16384/4 = 4096 blocks exact.
    skipgram_kernel<<<B_SIZE / 4, 128>>>(
        target, context, negs, in_embed, out_embed, out);
}